// round 7
// baseline (speedup 1.0000x reference)
#include <cuda_runtime.h>
#include <cuda_bf16.h>
#include <cstdint>

// BatchRankingLoss: G=511 groups of d=256 decoys.
// loss = sum_{g,i,j} w_ij * max(0, 1 + y_ij*(o_i - o_j)) / (G*d*(d-1))
//   y_ij = -1 if (t_i - t_j) < 0 else +1 ;  w_ij = |t_i - t_j| > 0.1
//
// Symmetry: term(i,j)==term(j,i) -> sum = 2 * sum over unordered pairs.
// Register blocking: each thread owns 4 consecutive rows r=4u+k (o,t in regs).
// One smem column load v = ot[4u+s] feeds 4 terms (m = s-k). Coverage per
// row k: m in [1,127] full weight + m=128 at half weight (distance-128 pairs
// are generated by both endpoints). Main loop s=4..127 is uniform full-weight;
// s=1..3 prologue and s=128..131 epilogue handle the triangle edges exactly.
// Shared array padded to 384 (first 128 rows duplicated) so no index wrap.
//
// 4 groups per 256-thread CTA -> grid=128 (one wave). Last CTA (ticket)
// reduces group sums and writes d_out; ticket reset -> replay-deterministic.

#define D      256
#define PAD    384
#define GPB    4        // groups per block
#define THRESH 0.1f

__device__ float    g_group_sums[4096];
__device__ unsigned g_ticket;   // zero-init; reset by last CTA each call

__device__ __forceinline__ void acc_term(float& acc, float oi, float ti, float2 v)
{
    const float dt = ti - v.y;
    const float dd = oi - v.x;
    // y*do via sign-bit xor (y = -1 iff dt < 0; dt==-0.0 is weighted out)
    const uint32_t s =
        __float_as_uint(dd) ^ (__float_as_uint(dt) & 0x80000000u);
    const float q = fmaxf(0.0f, 1.0f + __uint_as_float(s));
    if (fabsf(dt) > THRESH) acc += q;      // predicated FADD
}

__global__ __launch_bounds__(GPB * 64) void ranking_loss_kernel(
    const float* __restrict__ o_in,   // [B,1] -> [B]
    const float* __restrict__ t_in,   // [B]
    float* __restrict__ out,
    int G, int NC)
{
    __shared__ float2 ot[GPB][PAD];
    __shared__ float  wsum[GPB * 2];        // one slot per warp
    __shared__ bool   is_last;

    const int tid = threadIdx.x;
    const int sub = tid >> 6;               // group within block
    const int u   = tid & 63;               // row-block within group
    const int g   = blockIdx.x * GPB + sub;

    float4 o4 = make_float4(0.f, 0.f, 0.f, 0.f);
    float4 t4 = o4;
    if (g < G) {                            // invalid group -> zeros (dt==0 gated out)
        o4 = reinterpret_cast<const float4*>(o_in)[g * 64 + u];
        t4 = reinterpret_cast<const float4*>(t_in)[g * 64 + u];
    }

    float2* row = ot[sub];
    const int r = 4 * u;
    row[r + 0] = make_float2(o4.x, t4.x);
    row[r + 1] = make_float2(o4.y, t4.y);
    row[r + 2] = make_float2(o4.z, t4.z);
    row[r + 3] = make_float2(o4.w, t4.w);
    if (r < 128) {                          // duplicate first 128 rows -> no wrap
        row[D + r + 0] = make_float2(o4.x, t4.x);
        row[D + r + 1] = make_float2(o4.y, t4.y);
        row[D + r + 2] = make_float2(o4.z, t4.z);
        row[D + r + 3] = make_float2(o4.w, t4.w);
    }
    __syncthreads();

    const float2* col = row + r;            // col[s] = ot[sub][4u+s]
    float a0 = 0.f, a1 = 0.f, a2 = 0.f, a3 = 0.f, ah = 0.f;

    // prologue: s=1..3 (rows with m >= 1 only)
    { const float2 v = col[1]; acc_term(a0, o4.x, t4.x, v); }
    { const float2 v = col[2]; acc_term(a0, o4.x, t4.x, v);
                               acc_term(a1, o4.y, t4.y, v); }
    { const float2 v = col[3]; acc_term(a0, o4.x, t4.x, v);
                               acc_term(a1, o4.y, t4.y, v);
                               acc_term(a2, o4.z, t4.z, v); }

#pragma unroll 8
    for (int s = 4; s < 128; ++s) {         // all 4 rows, m in [1,127]
        const float2 v = col[s];
        acc_term(a0, o4.x, t4.x, v);
        acc_term(a1, o4.y, t4.y, v);
        acc_term(a2, o4.z, t4.z, v);
        acc_term(a3, o4.w, t4.w, v);
    }

    // epilogue: s=128..131 ; m==128 terms -> half-weight accumulator ah
    { const float2 v = col[128]; acc_term(ah, o4.x, t4.x, v);   // m=128
                                 acc_term(a1, o4.y, t4.y, v);   // m=127
                                 acc_term(a2, o4.z, t4.z, v);   // m=126
                                 acc_term(a3, o4.w, t4.w, v); } // m=125
    { const float2 v = col[129]; acc_term(ah, o4.y, t4.y, v);   // m=128
                                 acc_term(a2, o4.z, t4.z, v);
                                 acc_term(a3, o4.w, t4.w, v); }
    { const float2 v = col[130]; acc_term(ah, o4.z, t4.z, v);   // m=128
                                 acc_term(a3, o4.w, t4.w, v); }
    { const float2 v = col[131]; acc_term(ah, o4.w, t4.w, v); } // m=128

    float acc = (a0 + a1) + (a2 + a3) + 0.5f * ah;

    // reduce across the 64 threads of this group (2 warps)
#pragma unroll
    for (int off = 16; off > 0; off >>= 1)
        acc += __shfl_xor_sync(0xffffffffu, acc, off);
    if ((tid & 31) == 0) wsum[tid >> 5] = acc;
    __syncthreads();

    if (u == 0 && g < G)
        g_group_sums[g] = wsum[2 * sub] + wsum[2 * sub + 1];

    __threadfence();
    __syncthreads();
    if (tid == 0) {
        unsigned old = atomicAdd(&g_ticket, 1u);
        is_last = (old == (unsigned)(NC - 1));
    }
    __syncthreads();

    if (is_last) {
        __threadfence();                    // acquire other CTAs' sums
        float v = (tid < G) ? g_group_sums[tid] : 0.f;
        if (tid + 256 < G) v += g_group_sums[tid + 256];

#pragma unroll
        for (int off = 16; off > 0; off >>= 1)
            v += __shfl_xor_sync(0xffffffffu, v, off);
        if ((tid & 31) == 0) wsum[tid >> 5] = v;
        __syncthreads();

        if (tid == 0) {
            float s = 0.f;
#pragma unroll
            for (int w = 0; w < GPB * 2; ++w) s += wsum[w];
            const float inv_n = 1.0f / ((float)G * (float)D * (float)(D - 1));
            out[0] = 2.0f * s * inv_n;      // x2: unordered -> ordered pairs
            g_ticket = 0;                   // reset for next graph replay
        }
    }
}

extern "C" void kernel_launch(void* const* d_in, const int* in_sizes, int n_in,
                              void* d_out, int out_size)
{
    const float* o = (const float*)d_in[0];  // input  [B,1] f32
    const float* t = (const float*)d_in[1];  // gdt_ts [B]   f32
    float* out = (float*)d_out;

    const int B  = in_sizes[1];
    const int K  = B / D;            // 512
    const int G  = K - 1;            // 511 (reference skips final group)
    const int NC = (G + GPB - 1) / GPB;   // 128 CTAs

    ranking_loss_kernel<<<NC, GPB * 64>>>(o, t, out, G, NC);
}

// round 8
// speedup vs baseline: 1.2083x; 1.2083x over previous
#include <cuda_runtime.h>
#include <cuda_bf16.h>
#include <cstdint>

// BatchRankingLoss: G=511 groups of d=256 decoys.
// loss = sum_{g,i,j} w_ij * max(0, 1 + y_ij*(o_i - o_j)) / (G*d*(d-1))
//   y_ij = -1 if (t_i - t_j) < 0 else +1 ;  w_ij = |t_i - t_j| > 0.1
//
// Symmetry: term(i,j)==term(j,i) -> sum = 2 * sum over unordered pairs.
// Enumeration per row i: m=1..127 full weight, m=128 half weight (each
// distance-128 pair generated by both endpoints).
//
// Blocking/split: CTA = 128 threads = ONE group. u=tid&63 selects a 4-row
// block (rows 4u..4u+3, o/t in regs); h=tid>>6 splits the column range:
//   h=0: prologue s=1..3 + main s=4..65
//   h=1: main s=66..127 + epilogue s=128..131 (m=128 -> half-weight acc)
// (s is the column offset from the block base; row k sees m = s-k.)
// -> 511 CTAs x 4 warps = 2044 warps (fixes R6's occupancy collapse).
//
// Packed math: smem holds NEGATED o,t in separate float arrays, so for a
// column pair (s,s+1): dt2 = add.rn.f32x2(ti_dup, nt[s..s+1]) and
// dd2 = add.rn.f32x2(oi_dup, no[s..s+1]) — one instr for two subs each.
// Arrays padded to 384 (first 128 rows duplicated) so indices never wrap.
//
// Fused reduction: group sums -> scratch; last CTA (ticket) writes d_out and
// resets the ticket -> graph-replay deterministic.

#define D      256
#define PAD    384
#define THRESH 0.1f

__device__ float    g_group_sums[4096];
__device__ unsigned g_ticket;   // zero-init; reset by last CTA each call

__device__ __forceinline__ uint64_t f32x2_add(uint64_t a, uint64_t b)
{
    uint64_t r;
    asm("add.rn.f32x2 %0, %1, %2;" : "=l"(r) : "l"(a), "l"(b));
    return r;
}
__device__ __forceinline__ uint64_t pack2(float lo, float hi)
{
    uint64_t r;
    asm("mov.b64 %0, {%1, %2};" : "=l"(r) : "f"(lo), "f"(hi));
    return r;
}
__device__ __forceinline__ void unpack2(uint64_t v, float& lo, float& hi)
{
    asm("mov.b64 {%0, %1}, %2;" : "=f"(lo), "=f"(hi) : "l"(v));
}

__device__ __forceinline__ void acc_half(float& acc, float dt, float dd)
{
    // y*do via sign-bit xor (y=-1 iff dt<0; dt==+-0 is weighted out)
    const uint32_t s =
        __float_as_uint(dd) ^ (__float_as_uint(dt) & 0x80000000u);
    const float q = fmaxf(0.0f, 1.0f + __uint_as_float(s));
    if (fabsf(dt) > THRESH) acc += q;          // predicated FADD
}

// scalar term from negated smem values
__device__ __forceinline__ void acc_neg(float& acc, float oi, float ti,
                                        float noj, float ntj)
{
    acc_half(acc, ti + ntj, oi + noj);
}

__global__ __launch_bounds__(128) void ranking_loss_kernel(
    const float* __restrict__ o_in,   // [B,1] -> [B]
    const float* __restrict__ t_in,   // [B]
    float* __restrict__ out,
    int G)
{
    __shared__ __align__(16) float no_s[PAD];   // negated o
    __shared__ __align__(16) float nt_s[PAD];   // negated t
    __shared__ float wsum[4];
    __shared__ bool  is_last;

    const int tid = threadIdx.x;
    const int u   = tid & 63;          // 4-row block index
    const int h   = tid >> 6;          // column half
    const int g   = blockIdx.x;
    const int r   = 4 * u;

    const float4 o4 = reinterpret_cast<const float4*>(o_in)[g * 64 + u];
    const float4 t4 = reinterpret_cast<const float4*>(t_in)[g * 64 + u];

    if (h == 0) {                      // one writer per 4-row block
        no_s[r + 0] = -o4.x; no_s[r + 1] = -o4.y;
        no_s[r + 2] = -o4.z; no_s[r + 3] = -o4.w;
        nt_s[r + 0] = -t4.x; nt_s[r + 1] = -t4.y;
        nt_s[r + 2] = -t4.z; nt_s[r + 3] = -t4.w;
        if (r < 128) {                 // duplicate first 128 rows -> no wrap
            no_s[D + r + 0] = -o4.x; no_s[D + r + 1] = -o4.y;
            no_s[D + r + 2] = -o4.z; no_s[D + r + 3] = -o4.w;
            nt_s[D + r + 0] = -t4.x; nt_s[D + r + 1] = -t4.y;
            nt_s[D + r + 2] = -t4.z; nt_s[D + r + 3] = -t4.w;
        }
    }
    __syncthreads();

    const float* cno = no_s + r;       // cno[s] = -o[row r+s]
    const float* cnt = nt_s + r;

    const float oi[4] = {o4.x, o4.y, o4.z, o4.w};
    const float ti[4] = {t4.x, t4.y, t4.z, t4.w};
    uint64_t oi2[4], ti2[4];
#pragma unroll
    for (int k = 0; k < 4; ++k) {
        oi2[k] = pack2(oi[k], oi[k]);
        ti2[k] = pack2(ti[k], ti[k]);
    }

    float accA[4] = {0.f, 0.f, 0.f, 0.f};  // even-column accumulators
    float accB[4] = {0.f, 0.f, 0.f, 0.f};  // odd-column accumulators
    float ah = 0.f;                        // m=128 half-weight accumulator

    // main packed loop: 31 column pairs, s = s0, s0+2, ..., s0+60
    const int s0 = 4 + 62 * h;             // 4 (h=0) or 66 (h=1); even
#pragma unroll 31
    for (int p = 0; p < 31; ++p) {
        const int s = s0 + 2 * p;
        const uint64_t ntj2 =
            *reinterpret_cast<const uint64_t*>(cnt + s);   // LDS.64, 8B-aligned
        const uint64_t noj2 =
            *reinterpret_cast<const uint64_t*>(cno + s);
#pragma unroll
        for (int k = 0; k < 4; ++k) {
            float dtl, dth, ddl, ddh;
            unpack2(f32x2_add(ti2[k], ntj2), dtl, dth);
            unpack2(f32x2_add(oi2[k], noj2), ddl, ddh);
            acc_half(accA[k], dtl, ddl);
            acc_half(accB[k], dth, ddh);
        }
    }

    if (h == 0) {
        // prologue: s=1..3 (only rows with m = s-k >= 1)
        acc_neg(accA[0], oi[0], ti[0], cno[1], cnt[1]);
        acc_neg(accA[0], oi[0], ti[0], cno[2], cnt[2]);
        acc_neg(accA[1], oi[1], ti[1], cno[2], cnt[2]);
        acc_neg(accA[0], oi[0], ti[0], cno[3], cnt[3]);
        acc_neg(accA[1], oi[1], ti[1], cno[3], cnt[3]);
        acc_neg(accA[2], oi[2], ti[2], cno[3], cnt[3]);
    } else {
        // epilogue: s=128..131 ; m==128 terms -> half-weight acc
        acc_neg(ah,      oi[0], ti[0], cno[128], cnt[128]);   // m=128
        acc_neg(accA[1], oi[1], ti[1], cno[128], cnt[128]);   // m=127
        acc_neg(accA[2], oi[2], ti[2], cno[128], cnt[128]);   // m=126
        acc_neg(accA[3], oi[3], ti[3], cno[128], cnt[128]);   // m=125
        acc_neg(ah,      oi[1], ti[1], cno[129], cnt[129]);   // m=128
        acc_neg(accA[2], oi[2], ti[2], cno[129], cnt[129]);
        acc_neg(accA[3], oi[3], ti[3], cno[129], cnt[129]);
        acc_neg(ah,      oi[2], ti[2], cno[130], cnt[130]);   // m=128
        acc_neg(accA[3], oi[3], ti[3], cno[130], cnt[130]);
        acc_neg(ah,      oi[3], ti[3], cno[131], cnt[131]);   // m=128
    }

    float acc = ((accA[0] + accB[0]) + (accA[1] + accB[1]))
              + ((accA[2] + accB[2]) + (accA[3] + accB[3]))
              + 0.5f * ah;

    // CTA reduce (4 warps)
#pragma unroll
    for (int off = 16; off > 0; off >>= 1)
        acc += __shfl_xor_sync(0xffffffffu, acc, off);
    if ((tid & 31) == 0) wsum[tid >> 5] = acc;
    __syncthreads();

    if (tid == 0) {
        g_group_sums[g] = (wsum[0] + wsum[1]) + (wsum[2] + wsum[3]);
        __threadfence();
        unsigned old = atomicAdd(&g_ticket, 1u);
        is_last = (old == (unsigned)(G - 1));
    }
    __syncthreads();

    if (is_last) {
        __threadfence();                    // acquire other CTAs' sums
        float v = g_group_sums[tid]         // tid < 128 <= G
                + g_group_sums[tid + 128]
                + g_group_sums[tid + 256];
        if (tid + 384 < G) v += g_group_sums[tid + 384];

#pragma unroll
        for (int off = 16; off > 0; off >>= 1)
            v += __shfl_xor_sync(0xffffffffu, v, off);
        if ((tid & 31) == 0) wsum[tid >> 5] = v;
        __syncthreads();

        if (tid == 0) {
            const float s = (wsum[0] + wsum[1]) + (wsum[2] + wsum[3]);
            const float inv_n = 1.0f / ((float)G * (float)D * (float)(D - 1));
            out[0] = 2.0f * s * inv_n;      // x2: unordered -> ordered pairs
            g_ticket = 0;                   // reset for next graph replay
        }
    }
}

extern "C" void kernel_launch(void* const* d_in, const int* in_sizes, int n_in,
                              void* d_out, int out_size)
{
    const float* o = (const float*)d_in[0];  // input  [B,1] f32
    const float* t = (const float*)d_in[1];  // gdt_ts [B]   f32
    float* out = (float*)d_out;

    const int B = in_sizes[1];
    const int K = B / D;            // 512
    const int G = K - 1;            // 511 (reference skips final group)

    ranking_loss_kernel<<<G, 128>>>(o, t, out, G);
}